// round 2
// baseline (speedup 1.0000x reference)
#include <cuda_runtime.h>
#include <cstdint>

// GIKDWConv: depthwise 7x7 conv, stride 1, pad 3, weight symmetrized over the
// 4-fold rotation group. N=16, C=384, H=W=64, fp32.
//
// Strategy:
//  - one block per (n, channel-pair): grid (192, 16), 256 threads
//  - channels packed pairwise into f32x2; all math via fma.rn.f32x2 (FFMA2),
//    which doubles fp32 FMA throughput vs 3-reg FFMA on sm_103a
//  - rotation symmetry => only 13 unique weights, kept in registers
//  - 70x70 f32x2 halo tile in SMEM; each thread computes a 16-row x 1-col
//    strip, scanning 22 input rows with a 7-wide register window
//    (7 LDS.64 per input row feed up to 49 FFMA2 => smem not binding)

#define HH 64
#define WW 64
#define NN 16
#define CC 384
#define TILE 70            // 64 + 2*3 halo
#define RPT 16             // output rows per thread

// orbit id of each (ky,kx) tap under 90-degree rotation (13 unique)
__device__ constexpr int ORBIT[7][7] = {
    {0, 1, 2, 3, 4, 5, 0},
    {5, 6, 7, 8, 9, 6, 1},
    {4, 9,10,11,10, 7, 2},
    {3, 8,11,12,11, 8, 3},
    {2, 7,10,11,10, 9, 4},
    {1, 6, 9, 8, 7, 6, 5},
    {0, 5, 4, 3, 2, 1, 0}};
__device__ constexpr int REP_I[13] = {0,0,0,0,0,0,1,1,1,1,2,2,3};
__device__ constexpr int REP_J[13] = {0,1,2,3,4,5,1,2,3,4,2,3,3};

__device__ __forceinline__ unsigned long long fma2(unsigned long long a,
                                                   unsigned long long b,
                                                   unsigned long long c) {
    unsigned long long d;
    asm("fma.rn.f32x2 %0, %1, %2, %3;" : "=l"(d) : "l"(a), "l"(b), "l"(c));
    return d;
}

__device__ __forceinline__ unsigned long long pack2(float lo, float hi) {
    unsigned long long r;
    asm("mov.b64 %0, {%1, %2};" : "=l"(r) : "f"(lo), "f"(hi));
    return r;
}

__device__ __forceinline__ void unpack2(unsigned long long v, float& lo, float& hi) {
    asm("mov.b64 {%0, %1}, %2;" : "=f"(lo), "=f"(hi) : "l"(v));
}

__global__ __launch_bounds__(256, 2)
void gik_dwconv_kernel(const float* __restrict__ x,
                       const float* __restrict__ weight,
                       float* __restrict__ out) {
    __shared__ unsigned long long sx[TILE * TILE];  // packed (c0,c1) halo tile
    __shared__ unsigned long long sw[13];           // packed symmetric weights

    const int tid = threadIdx.x;
    const int cp  = blockIdx.x;        // channel pair 0..191
    const int n   = blockIdx.y;        // batch 0..15
    const int c0  = cp * 2;

    // ---- load halo tile (both channels, zero-padded) ----
    const float* x0 = x + ((n * CC + c0) * (HH * WW));
    const float* x1 = x0 + HH * WW;
    #pragma unroll 4
    for (int idx = tid; idx < TILE * TILE; idx += 256) {
        int r   = idx / TILE;
        int col = idx - r * TILE;
        int gy = r - 3, gx = col - 3;
        float v0 = 0.f, v1 = 0.f;
        if ((unsigned)gy < (unsigned)HH && (unsigned)gx < (unsigned)WW) {
            int off = gy * WW + gx;
            v0 = x0[off];
            v1 = x1[off];
        }
        sx[idx] = pack2(v0, v1);
    }

    // ---- compute the 13 unique symmetrized weights ----
    if (tid < 13) {
        const int i = REP_I[tid], j = REP_J[tid];
        const float* w0 = weight + c0 * 49;
        const float* w1 = w0 + 49;
        float a0 = 0.25f * (w0[i*7 + j] + w0[j*7 + (6-i)] +
                            w0[(6-i)*7 + (6-j)] + w0[(6-j)*7 + i]);
        float a1 = 0.25f * (w1[i*7 + j] + w1[j*7 + (6-i)] +
                            w1[(6-i)*7 + (6-j)] + w1[(6-j)*7 + i]);
        sw[tid] = pack2(a0, a1);
    }
    __syncthreads();

    // ---- per-thread strip: 16 output rows x 1 column (x 2 channels) ----
    const int cx = tid & 63;           // output column 0..63
    const int r0 = (tid >> 6) * RPT;   // output row base: 0,16,32,48

    unsigned long long wreg[13];
    #pragma unroll
    for (int o = 0; o < 13; o++) wreg[o] = sw[o];

    unsigned long long acc[RPT];
    #pragma unroll
    for (int r = 0; r < RPT; r++) acc[r] = 0ull;

    #pragma unroll
    for (int y = 0; y < RPT + 6; y++) {
        const unsigned long long* row = sx + (r0 + y) * TILE + cx;
        unsigned long long xv[7];
        #pragma unroll
        for (int t = 0; t < 7; t++) xv[t] = row[t];
        #pragma unroll
        for (int k = 0; k < 7; k++) {
            const int r = y - k;
            if (r >= 0 && r < RPT) {
                #pragma unroll
                for (int t = 0; t < 7; t++)
                    acc[r] = fma2(wreg[ORBIT[k][t]], xv[t], acc[r]);
            }
        }
    }

    // ---- store ----
    float* o0 = out + ((n * CC + c0) * (HH * WW));
    float* o1 = o0 + HH * WW;
    #pragma unroll
    for (int r = 0; r < RPT; r++) {
        float lo, hi;
        unpack2(acc[r], lo, hi);
        const int off = (r0 + r) * WW + cx;
        o0[off] = lo;
        o1[off] = hi;
    }
}

extern "C" void kernel_launch(void* const* d_in, const int* in_sizes, int n_in,
                              void* d_out, int out_size) {
    const float* x = (const float*)d_in[0];       // [16,384,64,64]
    const float* w = (const float*)d_in[1];       // [384,1,7,7]
    float* out = (float*)d_out;                   // [16,384,64,64]
    dim3 grid(CC / 2, NN);
    gik_dwconv_kernel<<<grid, 256>>>(x, w, out);
}

// round 3
// speedup vs baseline: 1.0496x; 1.0496x over previous
#include <cuda_runtime.h>
#include <cstdint>

// GIKDWConv: depthwise 7x7 conv, stride 1, pad 3, 4-fold-rotation-symmetrized
// weights. N=16, C=384, H=W=64, fp32.
//
// R3: 2 output columns x 8 output rows per thread, channels packed pairwise
// into f32x2 (fma.rn.f32x2). Row inputs loaded as 4x LDS.128 (aligned,
// conflict-free), double-buffered across the y-scan so LDS latency overlaps
// the FMA burst of the previous row.

#define HH 64
#define WW 64
#define NN 16
#define CC 384
#define TILE 70            // 64 + 2*3 halo
#define RPT 8              // output rows per thread
typedef unsigned long long ull;

// orbit id of each (ky,kx) tap under 90-degree rotation (13 unique weights)
__device__ constexpr int ORBIT[7][7] = {
    {0, 1, 2, 3, 4, 5, 0},
    {5, 6, 7, 8, 9, 6, 1},
    {4, 9,10,11,10, 7, 2},
    {3, 8,11,12,11, 8, 3},
    {2, 7,10,11,10, 9, 4},
    {1, 6, 9, 8, 7, 6, 5},
    {0, 5, 4, 3, 2, 1, 0}};
__device__ constexpr int REP_I[13] = {0,0,0,0,0,0,1,1,1,1,2,2,3};
__device__ constexpr int REP_J[13] = {0,1,2,3,4,5,1,2,3,4,2,3,3};

__device__ __forceinline__ ull fma2(ull a, ull b, ull c) {
    ull d;
    asm("fma.rn.f32x2 %0, %1, %2, %3;" : "=l"(d) : "l"(a), "l"(b), "l"(c));
    return d;
}
__device__ __forceinline__ ull pack2(float lo, float hi) {
    ull r;
    asm("mov.b64 %0, {%1, %2};" : "=l"(r) : "f"(lo), "f"(hi));
    return r;
}
__device__ __forceinline__ void unpack2(ull v, float& lo, float& hi) {
    asm("mov.b64 {%0, %1}, %2;" : "=f"(lo), "=f"(hi) : "l"(v));
}

__global__ __launch_bounds__(256, 2)
void gik_dwconv_kernel(const float* __restrict__ x,
                       const float* __restrict__ weight,
                       float* __restrict__ out) {
    __shared__ ull sx[TILE * TILE];  // packed (c0,c1) halo tile, 39.2 KB
    __shared__ ull sw[13];           // packed symmetric weights

    const int tid = threadIdx.x;
    const int cp  = blockIdx.x;        // channel pair 0..191
    const int n   = blockIdx.y;        // batch 0..15
    const int c0  = cp * 2;

    // ---- load halo tile (both channels, zero-padded) ----
    const float* x0 = x + ((n * CC + c0) * (HH * WW));
    const float* x1 = x0 + HH * WW;
    #pragma unroll 4
    for (int idx = tid; idx < TILE * TILE; idx += 256) {
        int r   = idx / TILE;
        int col = idx - r * TILE;
        int gy = r - 3, gx = col - 3;
        float v0 = 0.f, v1 = 0.f;
        if ((unsigned)gy < (unsigned)HH && (unsigned)gx < (unsigned)WW) {
            int off = gy * WW + gx;
            v0 = x0[off];
            v1 = x1[off];
        }
        sx[idx] = pack2(v0, v1);
    }

    // ---- the 13 unique symmetrized weights ----
    if (tid < 13) {
        const int i = REP_I[tid], j = REP_J[tid];
        const float* w0 = weight + c0 * 49;
        const float* w1 = w0 + 49;
        float a0 = 0.25f * (w0[i*7 + j] + w0[j*7 + (6-i)] +
                            w0[(6-i)*7 + (6-j)] + w0[(6-j)*7 + i]);
        float a1 = 0.25f * (w1[i*7 + j] + w1[j*7 + (6-i)] +
                            w1[(6-i)*7 + (6-j)] + w1[(6-j)*7 + i]);
        sw[tid] = pack2(a0, a1);
    }
    __syncthreads();

    // ---- per-thread: 8 output rows x 2 adjacent columns (x 2 channels) ----
    const int cx = (tid & 31) * 2;     // even output column 0..62
    const int r0 = (tid >> 5) * RPT;   // output row base: 0,8,...,56

    ull wreg[13];
    #pragma unroll
    for (int o = 0; o < 13; o++) wreg[o] = sw[o];

    ull acc0[RPT], acc1[RPT];          // col cx and cx+1
    #pragma unroll
    for (int r = 0; r < RPT; r++) { acc0[r] = 0ull; acc1[r] = 0ull; }

    // rolling window over RPT+6 = 14 input rows, double-buffered
    ull xv[2][8];
    {
        const ulonglong2* rp = (const ulonglong2*)(sx + r0 * TILE + cx);
        #pragma unroll
        for (int q = 0; q < 4; q++) {
            ulonglong2 v = rp[q];
            xv[0][2*q] = v.x; xv[0][2*q+1] = v.y;
        }
    }

    #pragma unroll
    for (int y = 0; y < RPT + 6; y++) {
        const int cur = y & 1, nxt = cur ^ 1;
        if (y < RPT + 5) {
            const ulonglong2* rp =
                (const ulonglong2*)(sx + (r0 + y + 1) * TILE + cx);
            #pragma unroll
            for (int q = 0; q < 4; q++) {
                ulonglong2 v = rp[q];
                xv[nxt][2*q] = v.x; xv[nxt][2*q+1] = v.y;
            }
        }
        #pragma unroll
        for (int k = 0; k < 7; k++) {
            const int r = y - k;
            if (r >= 0 && r < RPT) {
                #pragma unroll
                for (int t = 0; t < 7; t++) {
                    const ull w = wreg[ORBIT[k][t]];
                    acc0[r] = fma2(w, xv[cur][t],     acc0[r]);
                    acc1[r] = fma2(w, xv[cur][t + 1], acc1[r]);
                }
            }
        }
    }

    // ---- store: float2 per channel-row ----
    float* o0 = out + ((n * CC + c0) * (HH * WW));
    float* o1 = o0 + HH * WW;
    #pragma unroll
    for (int r = 0; r < RPT; r++) {
        float a, b, c, d;
        unpack2(acc0[r], a, b);   // a: c0 col cx, b: c1 col cx
        unpack2(acc1[r], c, d);   // c: c0 col cx+1, d: c1 col cx+1
        const int off = (r0 + r) * WW + cx;
        *(float2*)(o0 + off) = make_float2(a, c);
        *(float2*)(o1 + off) = make_float2(b, d);
    }
}

extern "C" void kernel_launch(void* const* d_in, const int* in_sizes, int n_in,
                              void* d_out, int out_size) {
    const float* x = (const float*)d_in[0];       // [16,384,64,64]
    const float* w = (const float*)d_in[1];       // [384,1,7,7]
    float* out = (float*)d_out;                   // [16,384,64,64]
    dim3 grid(CC / 2, NN);
    gik_dwconv_kernel<<<grid, 256>>>(x, w, out);
}

// round 4
// speedup vs baseline: 1.3077x; 1.2459x over previous
#include <cuda_runtime.h>
#include <cstdint>

// GIKDWConv: depthwise 7x7 conv, stride 1, pad 3, 4-fold-rotation-symmetrized
// weights. N=16, C=384, H=W=64, fp32.
//
// R4: occupancy push. Same f32x2 channel-pair math (fma.rn.f32x2), 2 cols x
// 8 rows per thread, but single-buffered row window to cut 16 registers and
// __launch_bounds__(256,3) to fit 3 CTAs/SM (24 warps). Latency hiding, not
// dataflow, was the binding constraint at 2 CTAs (issue 28.5%, fma 33%).

#define HH 64
#define WW 64
#define NN 16
#define CC 384
#define TILE 70            // 64 + 2*3 halo
#define RPT 8              // output rows per thread
typedef unsigned long long ull;

// orbit id of each (ky,kx) tap under 90-degree rotation (13 unique weights)
__device__ constexpr int ORBIT[7][7] = {
    {0, 1, 2, 3, 4, 5, 0},
    {5, 6, 7, 8, 9, 6, 1},
    {4, 9,10,11,10, 7, 2},
    {3, 8,11,12,11, 8, 3},
    {2, 7,10,11,10, 9, 4},
    {1, 6, 9, 8, 7, 6, 5},
    {0, 5, 4, 3, 2, 1, 0}};
__device__ constexpr int REP_I[13] = {0,0,0,0,0,0,1,1,1,1,2,2,3};
__device__ constexpr int REP_J[13] = {0,1,2,3,4,5,1,2,3,4,2,3,3};

__device__ __forceinline__ ull fma2(ull a, ull b, ull c) {
    ull d;
    asm("fma.rn.f32x2 %0, %1, %2, %3;" : "=l"(d) : "l"(a), "l"(b), "l"(c));
    return d;
}
__device__ __forceinline__ ull pack2(float lo, float hi) {
    ull r;
    asm("mov.b64 %0, {%1, %2};" : "=l"(r) : "f"(lo), "f"(hi));
    return r;
}
__device__ __forceinline__ void unpack2(ull v, float& lo, float& hi) {
    asm("mov.b64 {%0, %1}, %2;" : "=f"(lo), "=f"(hi) : "l"(v));
}

__global__ __launch_bounds__(256, 3)
void gik_dwconv_kernel(const float* __restrict__ x,
                       const float* __restrict__ weight,
                       float* __restrict__ out) {
    __shared__ ull sx[TILE * TILE];  // packed (c0,c1) halo tile, 39.2 KB
    __shared__ ull sw[13];           // packed symmetric weights

    const int tid = threadIdx.x;
    const int cp  = blockIdx.x;        // channel pair 0..191
    const int n   = blockIdx.y;        // batch 0..15
    const int c0  = cp * 2;

    // ---- load halo tile (both channels, zero-padded) ----
    const float* x0 = x + ((n * CC + c0) * (HH * WW));
    const float* x1 = x0 + HH * WW;
    #pragma unroll 4
    for (int idx = tid; idx < TILE * TILE; idx += 256) {
        int r   = idx / TILE;
        int col = idx - r * TILE;
        int gy = r - 3, gx = col - 3;
        float v0 = 0.f, v1 = 0.f;
        if ((unsigned)gy < (unsigned)HH && (unsigned)gx < (unsigned)WW) {
            int off = gy * WW + gx;
            v0 = x0[off];
            v1 = x1[off];
        }
        sx[idx] = pack2(v0, v1);
    }

    // ---- the 13 unique symmetrized weights ----
    if (tid < 13) {
        const int i = REP_I[tid], j = REP_J[tid];
        const float* w0 = weight + c0 * 49;
        const float* w1 = w0 + 49;
        float a0 = 0.25f * (w0[i*7 + j] + w0[j*7 + (6-i)] +
                            w0[(6-i)*7 + (6-j)] + w0[(6-j)*7 + i]);
        float a1 = 0.25f * (w1[i*7 + j] + w1[j*7 + (6-i)] +
                            w1[(6-i)*7 + (6-j)] + w1[(6-j)*7 + i]);
        sw[tid] = pack2(a0, a1);
    }
    __syncthreads();

    // ---- per-thread: 8 output rows x 2 adjacent columns (x 2 channels) ----
    const int cx = (tid & 31) * 2;     // even output column 0..62
    const int r0 = (tid >> 5) * RPT;   // output row base: 0,8,...,56

    ull wreg[13];
    #pragma unroll
    for (int o = 0; o < 13; o++) wreg[o] = sw[o];

    ull acc0[RPT], acc1[RPT];          // col cx and cx+1
    #pragma unroll
    for (int r = 0; r < RPT; r++) { acc0[r] = 0ull; acc1[r] = 0ull; }

    #pragma unroll
    for (int y = 0; y < RPT + 6; y++) {
        // 8 packed inputs for this row: 4x LDS.128, aligned (cx even)
        ull xv[8];
        {
            const ulonglong2* rp = (const ulonglong2*)(sx + (r0 + y) * TILE + cx);
            #pragma unroll
            for (int q = 0; q < 4; q++) {
                ulonglong2 v = rp[q];
                xv[2*q] = v.x; xv[2*q+1] = v.y;
            }
        }
        #pragma unroll
        for (int k = 0; k < 7; k++) {
            const int r = y - k;
            if (r >= 0 && r < RPT) {
                #pragma unroll
                for (int t = 0; t < 7; t++) {
                    const ull w = wreg[ORBIT[k][t]];
                    acc0[r] = fma2(w, xv[t],     acc0[r]);
                    acc1[r] = fma2(w, xv[t + 1], acc1[r]);
                }
            }
        }
    }

    // ---- store: float2 per channel-row ----
    float* o0 = out + ((n * CC + c0) * (HH * WW));
    float* o1 = o0 + HH * WW;
    #pragma unroll
    for (int r = 0; r < RPT; r++) {
        float a, b, c, d;
        unpack2(acc0[r], a, b);   // a: c0 col cx, b: c1 col cx
        unpack2(acc1[r], c, d);   // c: c0 col cx+1, d: c1 col cx+1
        const int off = (r0 + r) * WW + cx;
        *(float2*)(o0 + off) = make_float2(a, c);
        *(float2*)(o1 + off) = make_float2(b, d);
    }
}

extern "C" void kernel_launch(void* const* d_in, const int* in_sizes, int n_in,
                              void* d_out, int out_size) {
    const float* x = (const float*)d_in[0];       // [16,384,64,64]
    const float* w = (const float*)d_in[1];       // [384,1,7,7]
    float* out = (float*)d_out;                   // [16,384,64,64]
    dim3 grid(CC / 2, NN);
    gik_dwconv_kernel<<<grid, 256>>>(x, w, out);
}